// round 14
// baseline (speedup 1.0000x reference)
#include <cuda_runtime.h>
#include <cuda_fp16.h>
#include <math.h>

// Fixed-shape problem: B=4, N=50000, E=800000, D=64
#define NN 50000
#define BB 4
#define DD 64
#define NR (NN * BB)                 // 200000 rows (node-major: row = node*4 + b)
#define SCAN_B 196                   // ceil(50000/256)
#define GEMM_B ((NR + 127) / 128)    // 1563 blocks
#define AGM_B  ((NN + 31) / 32)      // 1563 blocks (32 nodes = 128 rows each)
#define FLAG_BIT 0x40000000
#define AP 72                        // padded smem row stride (halfs) = 144 B

// Scratch (__device__ globals per allocation-free rule)
// Tables hold s = (x@W)*dis[node], fp16, node chunks of 512 B.
__device__ uint4  g_xwh[(size_t)NR * 8];        // layer-1 scaled linear out, 25.6 MB
__device__ uint4  g_h1h[(size_t)NR * 8];        // layer-2 scaled linear out, 25.6 MB
__device__ float  g_dis[NN];                    // rsqrt(deg+1)
__device__ int    g_deg[NN];                    // zero-init; re-zeroed each pass
__device__ int    g_off[NN + 1];                // CSR offsets (by target node)
__device__ int    g_cur[NN];                    // fill cursors
__device__ __align__(16) unsigned g_edge[800000]; // src byte-offset (src*512)
__device__ int    g_pub[SCAN_B];                // lookback publications

static __device__ __forceinline__ unsigned smem_u32(const void* p) {
    return (unsigned)__cvta_generic_to_shared(p);
}

// fast tanh: 1 - 2*rcp(ex2(x*2*log2e)+1); MUFU-based, rel err ~1e-6.
static __device__ __forceinline__ float ftanh(float x) {
    float e;
    asm("ex2.approx.f32 %0, %1;" : "=f"(e) : "f"(x * 2.885390082f));
    float r;
    asm("rcp.approx.f32 %0, %1;" : "=f"(r) : "f"(e + 1.0f));
    return fmaf(-2.0f, r, 1.0f);
}

// ---------------------------------------------------------------------------
// degree count (4 edges/thread) + scan-flag reset
// ---------------------------------------------------------------------------
__global__ __launch_bounds__(256) void count_k(const int* __restrict__ ei, int E) {
    const int t = blockIdx.x * 256 + threadIdx.x;
    if (blockIdx.x == 0 && threadIdx.x < SCAN_B) g_pub[threadIdx.x] = 0;
    const int e4 = t * 4;
    if (e4 + 4 <= E) {
        const int4 c = __ldg((const int4*)(ei + E) + t);
        atomicAdd(&g_deg[c.x], 1);
        atomicAdd(&g_deg[c.y], 1);
        atomicAdd(&g_deg[c.z], 1);
        atomicAdd(&g_deg[c.w], 1);
    } else {
        for (int e = e4; e < E; e++) atomicAdd(&g_deg[ei[E + e]], 1);
    }
}

// ---------------------------------------------------------------------------
// single-pass exclusive scan (decoupled lookback); emits g_dis, re-zeroes g_deg
// ---------------------------------------------------------------------------
__global__ __launch_bounds__(256) void scan_k(int E) {
    __shared__ int sh[256];
    __shared__ int s_prefix;
    const int tid = threadIdx.x;
    const int b   = blockIdx.x;
    const int idx = b * 256 + tid;

    int v = 0;
    if (idx < NN) {
        v = g_deg[idx];
        g_deg[idx] = 0;
        g_dis[idx] = rsqrtf((float)(v + 1));
    }
    sh[tid] = v;
    __syncthreads();
#pragma unroll
    for (int o = 1; o < 256; o <<= 1) {
        int t2 = (tid >= o) ? sh[tid - o] : 0;
        __syncthreads();
        sh[tid] += t2;
        __syncthreads();
    }
    const int incl = sh[tid];
    const int total = sh[255];

    if (tid == 0) {
        s_prefix = 0;
        __threadfence();
        atomicExch(&g_pub[b], total | FLAG_BIT);
        if (b == 0) g_off[NN] = E;
    }
    __syncthreads();

    if (tid < b) {
        int p;
        do { p = atomicAdd(&g_pub[tid], 0); } while (!(p & FLAG_BIT));
        atomicAdd(&s_prefix, p & ~FLAG_BIT);
    }
    __syncthreads();

    if (idx < NN) {
        const int off = s_prefix + incl - v;
        g_off[idx] = off;
        g_cur[idx] = off;
    }
}

// ---------------------------------------------------------------------------
// fill body: record = src byte offset into feature table (src*512).
// ---------------------------------------------------------------------------
__device__ __forceinline__ void fill_body(const int* __restrict__ ei, int E, int blk) {
    const int t = blk * 256 + threadIdx.x;
    const int e4 = t * 4;
    if (e4 + 4 <= E) {
        const int4 r = __ldg((const int4*)ei + t);
        const int4 c = __ldg((const int4*)(ei + E) + t);
        int p0 = atomicAdd(&g_cur[c.x], 1);
        int p1 = atomicAdd(&g_cur[c.y], 1);
        int p2 = atomicAdd(&g_cur[c.z], 1);
        int p3 = atomicAdd(&g_cur[c.w], 1);
        g_edge[p0] = (unsigned)r.x * 512u;
        g_edge[p1] = (unsigned)r.y * 512u;
        g_edge[p2] = (unsigned)r.z * 512u;
        g_edge[p3] = (unsigned)r.w * 512u;
    } else {
        for (int e = e4; e < E; e++) {
            const int r = ei[e], c = ei[E + e];
            const int pos = atomicAdd(&g_cur[c], 1);
            g_edge[pos] = (unsigned)r * 512u;
        }
    }
}

// ---------------------------------------------------------------------------
// Shared MMA mainloop + scaled-fp16-store epilogue (m16n8k16, 128x64 tile).
// Reads A from As (must be filled + synced), W from Wsh. Stores (A@W)*dis
// as fp16 node-chunk layout into `outp`.
// ---------------------------------------------------------------------------
__device__ __forceinline__ void mma_and_store(const __half* As, const __half* Wsh,
                                              __half* outp, int base,
                                              int warp, int lane) {
    float acc[8][4];
#pragma unroll
    for (int t = 0; t < 8; t++)
#pragma unroll
        for (int r = 0; r < 4; r++) acc[t][r] = 0.0f;

#pragma unroll
    for (int k0 = 0; k0 < 64; k0 += 16) {
        unsigned a0, a1, a2, a3;
        {
            const int arow = warp * 16 + (lane & 15);
            const int acol = k0 + ((lane >> 4) << 3);
            const unsigned addrA = smem_u32(&As[arow * AP + acol]);
            asm volatile(
                "ldmatrix.sync.aligned.m8n8.x4.shared.b16 {%0,%1,%2,%3}, [%4];"
                : "=r"(a0), "=r"(a1), "=r"(a2), "=r"(a3) : "r"(addrA));
        }
#pragma unroll
        for (int nt = 0; nt < 8; nt += 2) {
            unsigned b0, b1, b2, b3;
            {
                const int l8  = lane & 7;
                const int sel = lane >> 3;
                const int brow = k0 + l8 + ((sel & 1) << 3);
                const int bcol = (nt + (sel >> 1)) * 8;
                const unsigned addrB = smem_u32(&Wsh[brow * AP + bcol]);
                asm volatile(
                    "ldmatrix.sync.aligned.m8n8.x4.trans.shared.b16 {%0,%1,%2,%3}, [%4];"
                    : "=r"(b0), "=r"(b1), "=r"(b2), "=r"(b3) : "r"(addrB));
            }
            asm volatile(
                "mma.sync.aligned.m16n8k16.row.col.f32.f16.f16.f32 "
                "{%0,%1,%2,%3}, {%4,%5,%6,%7}, {%8,%9}, {%0,%1,%2,%3};"
                : "+f"(acc[nt][0]), "+f"(acc[nt][1]), "+f"(acc[nt][2]), "+f"(acc[nt][3])
                : "r"(a0), "r"(a1), "r"(a2), "r"(a3), "r"(b0), "r"(b1));
            asm volatile(
                "mma.sync.aligned.m16n8k16.row.col.f32.f16.f16.f32 "
                "{%0,%1,%2,%3}, {%4,%5,%6,%7}, {%8,%9}, {%0,%1,%2,%3};"
                : "+f"(acc[nt + 1][0]), "+f"(acc[nt + 1][1]), "+f"(acc[nt + 1][2]), "+f"(acc[nt + 1][3])
                : "r"(a0), "r"(a1), "r"(a2), "r"(a3), "r"(b2), "r"(b3));
        }
    }

    const int g   = lane >> 2;
    const int tig = lane & 3;
    const int row_lo = base + warp * 16 + g;
    const int row_hi = row_lo + 8;
    if (row_lo < NR) {
        const float d = g_dis[row_lo >> 2];
        __half* p = outp + (size_t)row_lo * 64 + tig * 2;
#pragma unroll
        for (int nt = 0; nt < 8; nt++)
            *(__half2*)(p + nt * 8) = __floats2half2_rn(acc[nt][0] * d, acc[nt][1] * d);
    }
    if (row_hi < NR) {
        const float d = g_dis[row_hi >> 2];
        __half* p = outp + (size_t)row_hi * 64 + tig * 2;
#pragma unroll
        for (int nt = 0; nt < 8; nt++)
            *(__half2*)(p + nt * 8) = __floats2half2_rn(acc[nt][2] * d, acc[nt][3] * d);
    }
}

// ---------------------------------------------------------------------------
// GEMM1: 128 rows x 64 cols per block; x fp32 (B,N,D); writes g_xwh.
// ---------------------------------------------------------------------------
__device__ __forceinline__ void gemm1_body(const float* __restrict__ x,
                                           const float* __restrict__ W,
                                           int blk) {
    __shared__ __align__(16) __half As[128 * AP];   // 18.4 KB
    __shared__ __align__(16) __half Wsh[64 * AP];   // 9.2 KB
    const int tid  = threadIdx.x;
    const int warp = tid >> 5;
    const int lane = tid & 31;

    {
        const float4* W4 = (const float4*)W;
#pragma unroll
        for (int i = 0; i < 4; i++) {
            const int q = i * 256 + tid;
            const int row = q >> 4, c4 = q & 15;
            const float4 v = __ldg(W4 + q);
            *(__half2*)&Wsh[row * AP + c4 * 4]     = __floats2half2_rn(v.x, v.y);
            *(__half2*)&Wsh[row * AP + c4 * 4 + 2] = __floats2half2_rn(v.z, v.w);
        }
    }

    const int base = blk * 128;
#pragma unroll
    for (int i = 0; i < 8; i++) {
        const int q = i * 256 + tid;
        const int row = q >> 4, c4 = q & 15;
        int rr = base + row; if (rr >= NR) rr = NR - 1;
        const int n = rr >> 2, bb = rr & 3;
        const float4 v = __ldg((const float4*)(x + ((size_t)bb * NN + n) * DD) + c4);
        *(__half2*)&As[row * AP + c4 * 4]     = __floats2half2_rn(v.x, v.y);
        *(__half2*)&As[row * AP + c4 * 4 + 2] = __floats2half2_rn(v.z, v.w);
    }
    __syncthreads();

    mma_and_store(As, Wsh, (__half*)g_xwh, base, warp, lane);
}

// fused: gemm1 blocks [0, GEMM_B) + CSR-fill blocks [GEMM_B, ...)
__global__ __launch_bounds__(256) void gemmfill_k(const float* __restrict__ x,
                                                  const float* __restrict__ W,
                                                  const int* __restrict__ ei, int E) {
    if (blockIdx.x < GEMM_B) gemm1_body(x, W, blockIdx.x);
    else                     fill_body(ei, E, blockIdx.x - GEMM_B);
}

// ---------------------------------------------------------------------------
// Gather core: A[8] = s[node] + sum over in-edges of s[src], for this lane's
// 16-byte slice. xwb = table base + lane*16.
// ---------------------------------------------------------------------------
__device__ __forceinline__ void add_u4(float* A, const uint4 u) {
    const __half2* hp = (const __half2*)&u;
    const float2 f0 = __half22float2(hp[0]);
    const float2 f1 = __half22float2(hp[1]);
    const float2 f2 = __half22float2(hp[2]);
    const float2 f3 = __half22float2(hp[3]);
    A[0] += f0.x; A[1] += f0.y;
    A[2] += f1.x; A[3] += f1.y;
    A[4] += f2.x; A[5] += f2.y;
    A[6] += f3.x; A[7] += f3.y;
}

__device__ __forceinline__ void add_pair_u4(float* A, const uint4 a, const uint4 b) {
    const __half2* ha = (const __half2*)&a;
    const __half2* hb = (const __half2*)&b;
    uint4 s;
    __half2* hs = (__half2*)&s;
    hs[0] = __hadd2(ha[0], hb[0]);
    hs[1] = __hadd2(ha[1], hb[1]);
    hs[2] = __hadd2(ha[2], hb[2]);
    hs[3] = __hadd2(ha[3], hb[3]);
    add_u4(A, s);
}

__device__ __forceinline__ void gather_node(const char* __restrict__ xwb,
                                            int node, float* A) {
    // self term (already scaled by dis[node] in the table)
    {
        const uint4 u = __ldg((const uint4*)(xwb + (unsigned)node * 512u));
        const __half2* hp = (const __half2*)&u;
        const float2 f0 = __half22float2(hp[0]);
        const float2 f1 = __half22float2(hp[1]);
        const float2 f2 = __half22float2(hp[2]);
        const float2 f3 = __half22float2(hp[3]);
        A[0] = f0.x; A[1] = f0.y;
        A[2] = f1.x; A[3] = f1.y;
        A[4] = f2.x; A[5] = f2.y;
        A[6] = f3.x; A[7] = f3.y;
    }

    int j = g_off[node];
    const int end = g_off[node + 1];

    while (j < end && (j & 3)) {
        const unsigned off = __ldg(g_edge + j);
        add_u4(A, __ldg((const uint4*)(xwb + off)));
        j++;
    }

    uint4 rec;
    if (j + 4 <= end) rec = __ldg((const uint4*)(g_edge + j));
    while (j + 8 <= end) {
        const uint4 nrec = __ldg((const uint4*)(g_edge + j + 4));
        const uint4 v0 = __ldg((const uint4*)(xwb + rec.x));
        const uint4 v1 = __ldg((const uint4*)(xwb + rec.y));
        const uint4 v2 = __ldg((const uint4*)(xwb + rec.z));
        const uint4 v3 = __ldg((const uint4*)(xwb + rec.w));
        add_pair_u4(A, v0, v1);
        add_pair_u4(A, v2, v3);
        rec = nrec;
        j += 4;
    }
    if (j + 4 <= end) {
        const uint4 v0 = __ldg((const uint4*)(xwb + rec.x));
        const uint4 v1 = __ldg((const uint4*)(xwb + rec.y));
        const uint4 v2 = __ldg((const uint4*)(xwb + rec.z));
        const uint4 v3 = __ldg((const uint4*)(xwb + rec.w));
        add_pair_u4(A, v0, v1);
        add_pair_u4(A, v2, v3);
        j += 4;
    }
    if (j + 2 <= end) {
        const unsigned o0 = __ldg(g_edge + j);
        const unsigned o1 = __ldg(g_edge + j + 1);
        add_pair_u4(A, __ldg((const uint4*)(xwb + o0)), __ldg((const uint4*)(xwb + o1)));
        j += 2;
    }
    if (j < end) {
        const unsigned off = __ldg(g_edge + j);
        add_u4(A, __ldg((const uint4*)(xwb + off)));
    }
}

// ---------------------------------------------------------------------------
// FUSED agg1 + gemm2: each block gathers 32 nodes (warp-per-node x4) from
// g_xwh, applies bias1+tanh, writes fp16 h1 rows straight into the MMA
// A-tile, then computes (h1 @ W2)*dis -> g_h1h. No h1 global round-trip.
// ---------------------------------------------------------------------------
__global__ __launch_bounds__(256) void aggmm_k(const float* __restrict__ bias,
                                               const float* __restrict__ W) {
    __shared__ __align__(16) __half As[128 * AP];   // 18.4 KB
    __shared__ __align__(16) __half Wsh[64 * AP];   // 9.2 KB
    const int tid  = threadIdx.x;
    const int warp = tid >> 5;
    const int lane = tid & 31;

    // load W2
    {
        const float4* W4 = (const float4*)W;
#pragma unroll
        for (int i = 0; i < 4; i++) {
            const int q = i * 256 + tid;
            const int row = q >> 4, c4 = q & 15;
            const float4 v = __ldg(W4 + q);
            *(__half2*)&Wsh[row * AP + c4 * 4]     = __floats2half2_rn(v.x, v.y);
            *(__half2*)&Wsh[row * AP + c4 * 4 + 2] = __floats2half2_rn(v.z, v.w);
        }
    }

    const char* __restrict__ xwb = (const char*)g_xwh + (unsigned)lane * 16u;
    const float4 bv0 = __ldg((const float4*)bias + (lane & 7) * 2);
    const float4 bv1 = __ldg((const float4*)bias + (lane & 7) * 2 + 1);

    const int node0 = blockIdx.x * 32;
#pragma unroll 1
    for (int i = 0; i < 4; i++) {
        const int nl   = warp * 4 + i;           // node-local 0..31
        const int node = node0 + nl;
        const int lrow = nl * 4 + (lane >> 3);   // block-local row 0..127
        uint4 u = make_uint4(0u, 0u, 0u, 0u);
        if (node < NN) {
            float A[8];
            gather_node(xwb, node, A);
            const float dn = g_dis[node];
            float o[8];
            o[0] = ftanh(fmaf(dn, A[0], bv0.x)); o[1] = ftanh(fmaf(dn, A[1], bv0.y));
            o[2] = ftanh(fmaf(dn, A[2], bv0.z)); o[3] = ftanh(fmaf(dn, A[3], bv0.w));
            o[4] = ftanh(fmaf(dn, A[4], bv1.x)); o[5] = ftanh(fmaf(dn, A[5], bv1.y));
            o[6] = ftanh(fmaf(dn, A[6], bv1.z)); o[7] = ftanh(fmaf(dn, A[7], bv1.w));
            const __half2 p0 = __floats2half2_rn(o[0], o[1]);
            const __half2 p1 = __floats2half2_rn(o[2], o[3]);
            const __half2 p2 = __floats2half2_rn(o[4], o[5]);
            const __half2 p3 = __floats2half2_rn(o[6], o[7]);
            u.x = *(const unsigned*)&p0;
            u.y = *(const unsigned*)&p1;
            u.z = *(const unsigned*)&p2;
            u.w = *(const unsigned*)&p3;
        }
        *(uint4*)&As[lrow * AP + (lane & 7) * 8] = u;
    }
    __syncthreads();

    mma_and_store(As, Wsh, (__half*)g_h1h, blockIdx.x * 128, warp, lane);
}

// ---------------------------------------------------------------------------
// Final aggregation: gathers g_h1h, bias2 + tanh, writes fp32 out (B,N,D).
// ---------------------------------------------------------------------------
__global__ __launch_bounds__(256) void aggfin_k(const float* __restrict__ bias,
                                                float* __restrict__ dst) {
    const int node = blockIdx.x * 8 + (threadIdx.x >> 5);
    const int lane = threadIdx.x & 31;
    if (node >= NN) return;

    const char* __restrict__ xwb = (const char*)g_h1h + (unsigned)lane * 16u;
    float A[8];
    gather_node(xwb, node, A);

    const float dn = g_dis[node];
    const float4 bv0 = __ldg((const float4*)bias + (lane & 7) * 2);
    const float4 bv1 = __ldg((const float4*)bias + (lane & 7) * 2 + 1);
    float o[8];
    o[0] = ftanh(fmaf(dn, A[0], bv0.x)); o[1] = ftanh(fmaf(dn, A[1], bv0.y));
    o[2] = ftanh(fmaf(dn, A[2], bv0.z)); o[3] = ftanh(fmaf(dn, A[3], bv0.w));
    o[4] = ftanh(fmaf(dn, A[4], bv1.x)); o[5] = ftanh(fmaf(dn, A[5], bv1.y));
    o[6] = ftanh(fmaf(dn, A[6], bv1.z)); o[7] = ftanh(fmaf(dn, A[7], bv1.w));

    const int b = lane >> 3;
    float4* o4 = (float4*)dst + ((size_t)b * NN + node) * 16 + (lane & 7) * 2;
    o4[0] = make_float4(o[0], o[1], o[2], o[3]);
    o4[1] = make_float4(o[4], o[5], o[6], o[7]);
}

// ---------------------------------------------------------------------------
extern "C" void kernel_launch(void* const* d_in, const int* in_sizes, int n_in,
                              void* d_out, int out_size) {
    const float* h  = (const float*)d_in[1];
    const int*   ei = (const int*)d_in[2];
    const float* W1 = (const float*)d_in[3];
    const float* b1 = (const float*)d_in[4];
    const float* W2 = (const float*)d_in[5];
    const float* b2 = (const float*)d_in[6];
    float* out = (float*)d_out;

    const int E  = in_sizes[2] / 2;
    const int cB = (E / 4 + 255) / 256 + 1;
    const int aB = (NN + 7) / 8;

    count_k<<<cB, 256>>>(ei, E);                      // 1
    scan_k <<<SCAN_B, 256>>>(E);                      // 2
    gemmfill_k<<<GEMM_B + cB, 256>>>(h, W1, ei, E);   // 3 (gemm1 || fill)
    aggmm_k<<<AGM_B, 256>>>(b1, W2);                  // 4  <- profiled (agg1+gemm2)
    aggfin_k<<<aB, 256>>>(b2, out);                   // 5
}

// round 15
// speedup vs baseline: 1.0574x; 1.0574x over previous
#include <cuda_runtime.h>
#include <cuda_fp16.h>
#include <math.h>

// Fixed-shape problem: B=4, N=50000, E=800000, D=64
#define NN 50000
#define BB 4
#define DD 64
#define NR (NN * BB)                 // 200000 rows (node-major: row = node*4 + b)
#define SCAN_B 196                   // ceil(50000/256)
#define GEMM_B ((NR + 127) / 128)    // 1563 blocks
#define FLAG_BIT 0x40000000
#define AP 72                        // padded smem row stride (halfs) = 144 B

// Scratch (__device__ globals per allocation-free rule)
// Feature tables hold s = (x@W)*dis[node], fp16.
__device__ uint4  g_xwh[(size_t)NR * 8];        // scaled linear output, fp16, 25.6 MB
__device__ uint4  g_h1h[(size_t)NR * 8];        // layer-1 activation, fp16, 25.6 MB
__device__ float  g_dis[NN];                    // rsqrt(deg+1)
__device__ int    g_deg[NN];                    // zero-init; re-zeroed each pass
__device__ int    g_off[NN + 1];                // CSR offsets (by target node)
__device__ int    g_cur[NN];                    // fill cursors
__device__ __align__(16) unsigned g_edge[800000]; // src byte-offset (src*512)
__device__ int    g_pub[SCAN_B];                // lookback publications

static __device__ __forceinline__ unsigned smem_u32(const void* p) {
    return (unsigned)__cvta_generic_to_shared(p);
}

// fast tanh: 1 - 2*rcp(ex2(x*2*log2e)+1); MUFU-based, rel err ~1e-6.
static __device__ __forceinline__ float ftanh(float x) {
    float e;
    asm("ex2.approx.f32 %0, %1;" : "=f"(e) : "f"(x * 2.885390082f));
    float r;
    asm("rcp.approx.f32 %0, %1;" : "=f"(r) : "f"(e + 1.0f));
    return fmaf(-2.0f, r, 1.0f);
}

// ---------------------------------------------------------------------------
// degree count (4 edges/thread) + scan-flag reset
// ---------------------------------------------------------------------------
__global__ __launch_bounds__(256) void count_k(const int* __restrict__ ei, int E) {
    const int t = blockIdx.x * 256 + threadIdx.x;
    if (blockIdx.x == 0 && threadIdx.x < SCAN_B) g_pub[threadIdx.x] = 0;
    const int e4 = t * 4;
    if (e4 + 4 <= E) {
        const int4 c = __ldg((const int4*)(ei + E) + t);
        atomicAdd(&g_deg[c.x], 1);
        atomicAdd(&g_deg[c.y], 1);
        atomicAdd(&g_deg[c.z], 1);
        atomicAdd(&g_deg[c.w], 1);
    } else {
        for (int e = e4; e < E; e++) atomicAdd(&g_deg[ei[E + e]], 1);
    }
}

// ---------------------------------------------------------------------------
// single-pass exclusive scan (decoupled lookback); emits g_dis, re-zeroes g_deg
// ---------------------------------------------------------------------------
__global__ __launch_bounds__(256) void scan_k(int E) {
    __shared__ int sh[256];
    __shared__ int s_prefix;
    const int tid = threadIdx.x;
    const int b   = blockIdx.x;
    const int idx = b * 256 + tid;

    int v = 0;
    if (idx < NN) {
        v = g_deg[idx];
        g_deg[idx] = 0;
        g_dis[idx] = rsqrtf((float)(v + 1));
    }
    sh[tid] = v;
    __syncthreads();
#pragma unroll
    for (int o = 1; o < 256; o <<= 1) {
        int t2 = (tid >= o) ? sh[tid - o] : 0;
        __syncthreads();
        sh[tid] += t2;
        __syncthreads();
    }
    const int incl = sh[tid];
    const int total = sh[255];

    if (tid == 0) {
        s_prefix = 0;
        __threadfence();
        atomicExch(&g_pub[b], total | FLAG_BIT);
        if (b == 0) g_off[NN] = E;
    }
    __syncthreads();

    if (tid < b) {
        int p;
        do { p = atomicAdd(&g_pub[tid], 0); } while (!(p & FLAG_BIT));
        atomicAdd(&s_prefix, p & ~FLAG_BIT);
    }
    __syncthreads();

    if (idx < NN) {
        const int off = s_prefix + incl - v;
        g_off[idx] = off;
        g_cur[idx] = off;
    }
}

// ---------------------------------------------------------------------------
// fill body: record = src byte offset into feature table (src*512).
// ---------------------------------------------------------------------------
__device__ __forceinline__ void fill_body(const int* __restrict__ ei, int E, int blk) {
    const int t = blk * 256 + threadIdx.x;
    const int e4 = t * 4;
    if (e4 + 4 <= E) {
        const int4 r = __ldg((const int4*)ei + t);
        const int4 c = __ldg((const int4*)(ei + E) + t);
        int p0 = atomicAdd(&g_cur[c.x], 1);
        int p1 = atomicAdd(&g_cur[c.y], 1);
        int p2 = atomicAdd(&g_cur[c.z], 1);
        int p3 = atomicAdd(&g_cur[c.w], 1);
        g_edge[p0] = (unsigned)r.x * 512u;
        g_edge[p1] = (unsigned)r.y * 512u;
        g_edge[p2] = (unsigned)r.z * 512u;
        g_edge[p3] = (unsigned)r.w * 512u;
    } else {
        for (int e = e4; e < E; e++) {
            const int r = ei[e], c = ei[E + e];
            const int pos = atomicAdd(&g_cur[c], 1);
            g_edge[pos] = (unsigned)r * 512u;
        }
    }
}

// ---------------------------------------------------------------------------
// Tensor-core GEMM: 128 rows x 64 cols per 256-thread block (8 warps,
// 16 rows/warp), mma.sync m16n8k16 fp16 in / fp32 accum.
// Epilogue scales each output row by dis[row/4] before the fp16 store.
// MODE 0: x fp32 (B,N,D). MODE 1: x = g_h1h fp16. Output: g_xwh fp16.
// ---------------------------------------------------------------------------
template <int MODE>
__device__ __forceinline__ void gemm_body(const float* __restrict__ x,
                                          const float* __restrict__ W,
                                          int blk) {
    __shared__ __align__(16) __half As[128 * AP];   // 18.4 KB
    __shared__ __align__(16) __half Wsh[64 * AP];   // 9.2 KB
    const int tid  = threadIdx.x;
    const int warp = tid >> 5;
    const int lane = tid & 31;

    {
        const float4* W4 = (const float4*)W;
#pragma unroll
        for (int i = 0; i < 4; i++) {
            const int q = i * 256 + tid;
            const int row = q >> 4, c4 = q & 15;
            const float4 v = __ldg(W4 + q);
            *(__half2*)&Wsh[row * AP + c4 * 4]     = __floats2half2_rn(v.x, v.y);
            *(__half2*)&Wsh[row * AP + c4 * 4 + 2] = __floats2half2_rn(v.z, v.w);
        }
    }

    const int base = blk * 128;
    if (MODE == 0) {
#pragma unroll
        for (int i = 0; i < 8; i++) {
            const int q = i * 256 + tid;
            const int row = q >> 4, c4 = q & 15;
            int rr = base + row; if (rr >= NR) rr = NR - 1;
            const int n = rr >> 2, bb = rr & 3;
            const float4 v = __ldg((const float4*)(x + ((size_t)bb * NN + n) * DD) + c4);
            *(__half2*)&As[row * AP + c4 * 4]     = __floats2half2_rn(v.x, v.y);
            *(__half2*)&As[row * AP + c4 * 4 + 2] = __floats2half2_rn(v.z, v.w);
        }
    } else {
#pragma unroll
        for (int i = 0; i < 4; i++) {
            const int q = i * 256 + tid;
            const int row = q >> 3, u4 = q & 7;
            int rr = base + row; if (rr >= NR) rr = NR - 1;
            const uint4 u = __ldg(&g_h1h[(size_t)rr * 8 + u4]);
            *(uint4*)&As[row * AP + u4 * 8] = u;
        }
    }
    __syncthreads();

    float acc[8][4];
#pragma unroll
    for (int t = 0; t < 8; t++)
#pragma unroll
        for (int r = 0; r < 4; r++) acc[t][r] = 0.0f;

#pragma unroll
    for (int k0 = 0; k0 < 64; k0 += 16) {
        unsigned a0, a1, a2, a3;
        {
            const int arow = warp * 16 + (lane & 15);
            const int acol = k0 + ((lane >> 4) << 3);
            const unsigned addrA = smem_u32(&As[arow * AP + acol]);
            asm volatile(
                "ldmatrix.sync.aligned.m8n8.x4.shared.b16 {%0,%1,%2,%3}, [%4];"
                : "=r"(a0), "=r"(a1), "=r"(a2), "=r"(a3) : "r"(addrA));
        }
#pragma unroll
        for (int nt = 0; nt < 8; nt += 2) {
            unsigned b0, b1, b2, b3;
            {
                const int l8  = lane & 7;
                const int sel = lane >> 3;
                const int brow = k0 + l8 + ((sel & 1) << 3);
                const int bcol = (nt + (sel >> 1)) * 8;
                const unsigned addrB = smem_u32(&Wsh[brow * AP + bcol]);
                asm volatile(
                    "ldmatrix.sync.aligned.m8n8.x4.trans.shared.b16 {%0,%1,%2,%3}, [%4];"
                    : "=r"(b0), "=r"(b1), "=r"(b2), "=r"(b3) : "r"(addrB));
            }
            asm volatile(
                "mma.sync.aligned.m16n8k16.row.col.f32.f16.f16.f32 "
                "{%0,%1,%2,%3}, {%4,%5,%6,%7}, {%8,%9}, {%0,%1,%2,%3};"
                : "+f"(acc[nt][0]), "+f"(acc[nt][1]), "+f"(acc[nt][2]), "+f"(acc[nt][3])
                : "r"(a0), "r"(a1), "r"(a2), "r"(a3), "r"(b0), "r"(b1));
            asm volatile(
                "mma.sync.aligned.m16n8k16.row.col.f32.f16.f16.f32 "
                "{%0,%1,%2,%3}, {%4,%5,%6,%7}, {%8,%9}, {%0,%1,%2,%3};"
                : "+f"(acc[nt + 1][0]), "+f"(acc[nt + 1][1]), "+f"(acc[nt + 1][2]), "+f"(acc[nt + 1][3])
                : "r"(a0), "r"(a1), "r"(a2), "r"(a3), "r"(b2), "r"(b3));
        }
    }

    {
        __half* xwp = (__half*)g_xwh;
        const int g   = lane >> 2;
        const int tig = lane & 3;
        const int row_lo = base + warp * 16 + g;
        const int row_hi = row_lo + 8;
        if (row_lo < NR) {
            const float d = g_dis[row_lo >> 2];
            __half* p = xwp + (size_t)row_lo * 64 + tig * 2;
#pragma unroll
            for (int nt = 0; nt < 8; nt++)
                *(__half2*)(p + nt * 8) = __floats2half2_rn(acc[nt][0] * d, acc[nt][1] * d);
        }
        if (row_hi < NR) {
            const float d = g_dis[row_hi >> 2];
            __half* p = xwp + (size_t)row_hi * 64 + tig * 2;
#pragma unroll
            for (int nt = 0; nt < 8; nt++)
                *(__half2*)(p + nt * 8) = __floats2half2_rn(acc[nt][2] * d, acc[nt][3] * d);
        }
    }
}

// fused: gemm1 blocks [0, GEMM_B) + CSR-fill blocks [GEMM_B, ...)
__global__ __launch_bounds__(256) void gemmfill_k(const float* __restrict__ x,
                                                  const float* __restrict__ W,
                                                  const int* __restrict__ ei, int E) {
    if (blockIdx.x < GEMM_B) gemm_body<0>(x, W, blockIdx.x);
    else                     fill_body(ei, E, blockIdx.x - GEMM_B);
}

__global__ __launch_bounds__(256) void gemm2_k(const float* __restrict__ W) {
    gemm_body<1>(nullptr, W, blockIdx.x);
}

// ---------------------------------------------------------------------------
// Aggregation: warp per node; lane owns uint4 slice `lane` (8 halfs).
// Pure gather-sum; 4-edge batches pre-reduced as a QUAD fp16 tree (HADD2),
// then one fp32 accumulate. Epilogue applies dis[node] + bias + tanh.
// ---------------------------------------------------------------------------
__device__ __forceinline__ void add_u4(float* A, const uint4 u) {
    const __half2* hp = (const __half2*)&u;
    const float2 f0 = __half22float2(hp[0]);
    const float2 f1 = __half22float2(hp[1]);
    const float2 f2 = __half22float2(hp[2]);
    const float2 f3 = __half22float2(hp[3]);
    A[0] += f0.x; A[1] += f0.y;
    A[2] += f1.x; A[3] += f1.y;
    A[4] += f2.x; A[5] += f2.y;
    A[6] += f3.x; A[7] += f3.y;
}

__device__ __forceinline__ void add_pair_u4(float* A, const uint4 a, const uint4 b) {
    const __half2* ha = (const __half2*)&a;
    const __half2* hb = (const __half2*)&b;
    uint4 s;
    __half2* hs = (__half2*)&s;
    hs[0] = __hadd2(ha[0], hb[0]);
    hs[1] = __hadd2(ha[1], hb[1]);
    hs[2] = __hadd2(ha[2], hb[2]);
    hs[3] = __hadd2(ha[3], hb[3]);
    add_u4(A, s);
}

// quad fp16 tree: ((a+b) + (c+d)) in fp16, single fp32 accumulate
__device__ __forceinline__ void add_quad_u4(float* A, const uint4 a, const uint4 b,
                                            const uint4 c, const uint4 d) {
    const __half2* ha = (const __half2*)&a;
    const __half2* hb = (const __half2*)&b;
    const __half2* hc = (const __half2*)&c;
    const __half2* hd = (const __half2*)&d;
    uint4 s;
    __half2* hs = (__half2*)&s;
    hs[0] = __hadd2(__hadd2(ha[0], hb[0]), __hadd2(hc[0], hd[0]));
    hs[1] = __hadd2(__hadd2(ha[1], hb[1]), __hadd2(hc[1], hd[1]));
    hs[2] = __hadd2(__hadd2(ha[2], hb[2]), __hadd2(hc[2], hd[2]));
    hs[3] = __hadd2(__hadd2(ha[3], hb[3]), __hadd2(hc[3], hd[3]));
    add_u4(A, s);
}

template <bool FINAL>
__global__ __launch_bounds__(256) void agg_k(const float* __restrict__ bias,
                                             float* __restrict__ dst) {
    const int node = blockIdx.x * 8 + (threadIdx.x >> 5);
    const int lane = threadIdx.x & 31;
    if (node >= NN) return;

    const char* __restrict__ xwb = (const char*)g_xwh + (unsigned)lane * 16u;
    float A[8];

    // self term: s[node] (already scaled by dis[node])
    {
        const uint4 u = __ldg((const uint4*)(xwb + (unsigned)node * 512u));
        const __half2* hp = (const __half2*)&u;
        const float2 f0 = __half22float2(hp[0]);
        const float2 f1 = __half22float2(hp[1]);
        const float2 f2 = __half22float2(hp[2]);
        const float2 f3 = __half22float2(hp[3]);
        A[0] = f0.x; A[1] = f0.y;
        A[2] = f1.x; A[3] = f1.y;
        A[4] = f2.x; A[5] = f2.y;
        A[6] = f3.x; A[7] = f3.y;
    }

    int j = g_off[node];
    const int end = g_off[node + 1];

    // alignment prologue: advance to 16B-aligned record index
    while (j < end && (j & 3)) {
        const unsigned off = __ldg(g_edge + j);
        add_u4(A, __ldg((const uint4*)(xwb + off)));
        j++;
    }

    // software-pipelined main loop: 4 records per LDG.128, quad fp16 tree
    uint4 rec;
    if (j + 4 <= end) rec = __ldg((const uint4*)(g_edge + j));
    while (j + 8 <= end) {
        const uint4 nrec = __ldg((const uint4*)(g_edge + j + 4));
        const uint4 v0 = __ldg((const uint4*)(xwb + rec.x));
        const uint4 v1 = __ldg((const uint4*)(xwb + rec.y));
        const uint4 v2 = __ldg((const uint4*)(xwb + rec.z));
        const uint4 v3 = __ldg((const uint4*)(xwb + rec.w));
        add_quad_u4(A, v0, v1, v2, v3);
        rec = nrec;
        j += 4;
    }
    if (j + 4 <= end) {
        const uint4 v0 = __ldg((const uint4*)(xwb + rec.x));
        const uint4 v1 = __ldg((const uint4*)(xwb + rec.y));
        const uint4 v2 = __ldg((const uint4*)(xwb + rec.z));
        const uint4 v3 = __ldg((const uint4*)(xwb + rec.w));
        add_quad_u4(A, v0, v1, v2, v3);
        j += 4;
    }
    // tail (<=3)
    if (j + 2 <= end) {
        const unsigned o0 = __ldg(g_edge + j);
        const unsigned o1 = __ldg(g_edge + j + 1);
        add_pair_u4(A, __ldg((const uint4*)(xwb + o0)), __ldg((const uint4*)(xwb + o1)));
        j += 2;
    }
    if (j < end) {
        const unsigned off = __ldg(g_edge + j);
        add_u4(A, __ldg((const uint4*)(xwb + off)));
    }

    // epilogue: out = tanh(dis[node]*A + bias)
    const float dn = g_dis[node];
    const float4 bv0 = __ldg((const float4*)bias + (lane & 7) * 2);
    const float4 bv1 = __ldg((const float4*)bias + (lane & 7) * 2 + 1);
    float o[8];
    o[0] = ftanh(fmaf(dn, A[0], bv0.x)); o[1] = ftanh(fmaf(dn, A[1], bv0.y));
    o[2] = ftanh(fmaf(dn, A[2], bv0.z)); o[3] = ftanh(fmaf(dn, A[3], bv0.w));
    o[4] = ftanh(fmaf(dn, A[4], bv1.x)); o[5] = ftanh(fmaf(dn, A[5], bv1.y));
    o[6] = ftanh(fmaf(dn, A[6], bv1.z)); o[7] = ftanh(fmaf(dn, A[7], bv1.w));

    if (FINAL) {
        const int b = lane >> 3;
        float4* o4 = (float4*)dst + ((size_t)b * NN + node) * 16 + (lane & 7) * 2;
        o4[0] = make_float4(o[0], o[1], o[2], o[3]);
        o4[1] = make_float4(o[4], o[5], o[6], o[7]);
    } else {
        const __half2 p0 = __floats2half2_rn(o[0], o[1]);
        const __half2 p1 = __floats2half2_rn(o[2], o[3]);
        const __half2 p2 = __floats2half2_rn(o[4], o[5]);
        const __half2 p3 = __floats2half2_rn(o[6], o[7]);
        uint4 u;
        u.x = *(const unsigned int*)&p0;
        u.y = *(const unsigned int*)&p1;
        u.z = *(const unsigned int*)&p2;
        u.w = *(const unsigned int*)&p3;
        g_h1h[(size_t)node * 32 + lane] = u;
    }
}

// ---------------------------------------------------------------------------
extern "C" void kernel_launch(void* const* d_in, const int* in_sizes, int n_in,
                              void* d_out, int out_size) {
    const float* h  = (const float*)d_in[1];
    const int*   ei = (const int*)d_in[2];
    const float* W1 = (const float*)d_in[3];
    const float* b1 = (const float*)d_in[4];
    const float* W2 = (const float*)d_in[5];
    const float* b2 = (const float*)d_in[6];
    float* out = (float*)d_out;

    const int E  = in_sizes[2] / 2;
    const int cB = (E / 4 + 255) / 256 + 1;
    const int aB = (NN + 7) / 8;

    count_k<<<cB, 256>>>(ei, E);                      // 1
    scan_k <<<SCAN_B, 256>>>(E);                      // 2
    gemmfill_k<<<GEMM_B + cB, 256>>>(h, W1, ei, E);   // 3 (gemm1 || fill)
    agg_k<false><<<aB, 256>>>(b1, nullptr);           // 4  <- profiled
    gemm2_k<<<GEMM_B, 256>>>(W2);                     // 5
    agg_k<true> <<<aB, 256>>>(b2, out);               // 6
}